// round 12
// baseline (speedup 1.0000x reference)
#include <cuda_runtime.h>
#include <cstdint>

// FrequencyAttention fused tf32-mma kernel, v3:
// 2 batch elements / 256 threads per CTA, 2 CTAs/SM (phase overlap across CTAs).
// Single weight panel; stats region aliases the dead panel after last GEMM.

#define BATCH 8192
#define CCH   128
#define NB    32
#define ATT_SCALE 0.17677669529663687f   // 1/sqrt(32)
#define BN_EPS 1e-5f
#define MTOT  (BATCH * NB)

// ---- shared memory layout (float offsets) ----
#define XS_PAD 36
#define XS_EL  (128 * XS_PAD)            // 4608
#define XS_OFF 0                          // x -> Q -> att : [2][128][36]
#define KV_PAD 33
#define KV_EL  (128 * KV_PAD)            // 4224
#define KS_OFF (2 * XS_EL)               // 9216   K (later P) : [2][128][33]
#define VS_OFF (KS_OFF + 2 * KV_EL)      // 17664  V : [2][128][33]
#define PN_PAD 20
#define PN_OFF (VS_OFF + 2 * KV_EL)      // 26112  weight panel [128][20] (2560)
#define ST_OFF PN_OFF                    // stats alias panel (dead after last GEMM)
#define RL_OFF (PN_OFF + 128 * PN_PAD)   // 28672  rel bias (252 used)
#define SM_FLOATS (RL_OFF + 256)         // 28928 floats = 115712 B  (x2 CTAs = 231424)

// scratch: [0..127] sum, [128..255] sumsq, [256..383] scale, [384..511] shift
__device__ float g_stats[512];

__global__ void zero_stats_kernel() { g_stats[threadIdx.x] = 0.0f; }

__device__ __forceinline__ unsigned f2tf(float f) {
    unsigned u;
    asm("cvt.rna.tf32.f32 %0, %1;" : "=r"(u) : "f"(f));
    return u;
}

__device__ __forceinline__ float2 tf2pair(float a, float b) {
    float2 r;
    r.x = __uint_as_float(f2tf(a));
    r.y = __uint_as_float(f2tf(b));
    return r;
}

__device__ __forceinline__ void mma8(float c[4],
                                     unsigned a0, unsigned a1, unsigned a2, unsigned a3,
                                     unsigned b0, unsigned b1) {
    asm volatile(
        "mma.sync.aligned.m16n8k8.row.col.f32.tf32.tf32.f32 "
        "{%0,%1,%2,%3},{%4,%5,%6,%7},{%8,%9},{%0,%1,%2,%3};\n"
        : "+f"(c[0]), "+f"(c[1]), "+f"(c[2]), "+f"(c[3])
        : "r"(a0), "r"(a1), "r"(a2), "r"(a3), "r"(b0), "r"(b1));
}

// M=128, N=64 (2 els x 32 bins), K=128 GEMM. A = row-major f32 weights via
// single smem panel. 8 warps: warp tile 32x32 (wm=warp>>1 M quarter, wn=warp&1 el).
__device__ __forceinline__ void do_gemm(const float* __restrict__ W,
                                        float C[2][4][4], float* smf,
                                        int tid, int wm, int wn, int g, int tig)
{
    float* panel = smf + PN_OFF;
    const float* B = smf + XS_OFF + wn * XS_EL;

    #pragma unroll
    for (int mt = 0; mt < 2; ++mt)
        #pragma unroll
        for (int nt = 0; nt < 4; ++nt)
            #pragma unroll
            for (int r = 0; r < 4; ++r) C[mt][nt][r] = 0.0f;

    const int pr = tid >> 1;             // panel row (0..127), 2 threads/row
    const int pc = (tid & 1) * 8;        // col chunk (8 floats)
    const float* wrow = W + pr * 128 + pc;

    float4 w0 = __ldg((const float4*)(wrow));
    float4 w1 = __ldg((const float4*)(wrow) + 1);

    for (int ks = 0; ks < 8; ++ks) {
        __syncthreads();                  // previous panel fully consumed
        {
            unsigned* pp = (unsigned*)(panel + pr * PN_PAD + pc);
            uint4 u0 = make_uint4(f2tf(w0.x), f2tf(w0.y), f2tf(w0.z), f2tf(w0.w));
            uint4 u1 = make_uint4(f2tf(w1.x), f2tf(w1.y), f2tf(w1.z), f2tf(w1.w));
            ((uint4*)pp)[0] = u0;
            ((uint4*)pp)[1] = u1;
        }
        __syncthreads();
        if (ks < 7) {                     // prefetch next k-slice (overlaps mma)
            const float* wn_ = wrow + (ks + 1) * 16;
            w0 = __ldg((const float4*)(wn_));
            w1 = __ldg((const float4*)(wn_) + 1);
        }
        #pragma unroll
        for (int kk = 0; kk < 2; ++kk) {
            unsigned bf[4][2];
            #pragma unroll
            for (int nt = 0; nt < 4; ++nt) {
                const float* bp = B + (ks * 16 + kk * 8 + tig) * XS_PAD + nt * 8 + g;
                bf[nt][0] = __float_as_uint(bp[0]);
                bf[nt][1] = __float_as_uint(bp[4 * XS_PAD]);
            }
            #pragma unroll
            for (int mt = 0; mt < 2; ++mt) {
                const float* ap = panel + (wm * 32 + mt * 16 + g) * PN_PAD + kk * 8 + tig;
                unsigned a0 = __float_as_uint(ap[0]);
                unsigned a1 = __float_as_uint(ap[8 * PN_PAD]);
                unsigned a2 = __float_as_uint(ap[4]);
                unsigned a3 = __float_as_uint(ap[8 * PN_PAD + 4]);
                #pragma unroll
                for (int nt = 0; nt < 4; ++nt)
                    mma8(C[mt][nt], a0, a1, a2, a3, bf[nt][0], bf[nt][1]);
            }
        }
    }
}

// Store C (+bias, tf32) into KV region (pad 33 = odd -> scalar stores ONLY;
// float2 here traps on misaligned ST.64 — R6 lesson).
__device__ __forceinline__ void store_kv(const float C[2][4][4], float* dst,
                                         const float* __restrict__ bias,
                                         int wm, int g, int tig)
{
    #pragma unroll
    for (int mt = 0; mt < 2; ++mt) {
        const int r0 = wm * 32 + mt * 16 + g;
        const float bz0 = __ldg(bias + r0);
        const float bz1 = __ldg(bias + r0 + 8);
        #pragma unroll
        for (int nt = 0; nt < 4; ++nt) {
            const int m = nt * 8 + 2 * tig;
            dst[r0 * KV_PAD + m]           = __uint_as_float(f2tf(C[mt][nt][0] + bz0));
            dst[r0 * KV_PAD + m + 1]       = __uint_as_float(f2tf(C[mt][nt][1] + bz0));
            dst[(r0 + 8) * KV_PAD + m]     = __uint_as_float(f2tf(C[mt][nt][2] + bz1));
            dst[(r0 + 8) * KV_PAD + m + 1] = __uint_as_float(f2tf(C[mt][nt][3] + bz1));
        }
    }
}

__global__ __launch_bounds__(256, 2)
void fa_main_kernel(const float* __restrict__ x,
                    const float* __restrict__ qkv_w,
                    const float* __restrict__ qkv_b,
                    const float* __restrict__ out_w,
                    const float* __restrict__ out_b,
                    const float* __restrict__ rel,
                    float* __restrict__ out)
{
    extern __shared__ float smf[];
    const int tid  = threadIdx.x;
    const int warp = tid >> 5;           // 0..7
    const int lane = tid & 31;
    const int g    = lane >> 2;          // groupID (0..7)
    const int tig  = lane & 3;           // thread-in-group (0..3)
    const int wm   = warp >> 1;          // 0..3  (M quarter)
    const int wn   = warp & 1;           // 0..1  (el)
    const int b0   = blockIdx.x * 2;

    // ---- stage rel bias ----
    if (tid < 252) smf[RL_OFF + tid] = __ldg(&rel[tid]);

    // ---- load x (2 els) into XS as tf32 bits ----
    {
        const float4* xg = (const float4*)(x + (size_t)b0 * (CCH * NB));
        #pragma unroll
        for (int j = 0; j < 8; ++j) {
            const int i4  = tid + j * 256;          // 2048 float4 total
            float4 v = __ldg(xg + i4);
            const int el  = i4 >> 10;
            const int c   = (i4 >> 3) & 127;
            const int bn  = (i4 & 7) * 4;
            unsigned* d = (unsigned*)(smf + XS_OFF + el * XS_EL + c * XS_PAD + bn);
            ((uint4*)d)[0] = make_uint4(f2tf(v.x), f2tf(v.y), f2tf(v.z), f2tf(v.w));
        }
    }
    __syncthreads();

    float C[2][4][4];

    // ---- K rows (QKV rows 128..255) ----
    do_gemm(qkv_w + 128 * 128, C, smf, tid, wm, wn, g, tig);
    store_kv(C, smf + KS_OFF + wn * KV_EL, qkv_b + 128, wm, g, tig);

    // ---- V rows (QKV rows 256..383) ----
    do_gemm(qkv_w + 256 * 128, C, smf, tid, wm, wn, g, tig);
    store_kv(C, smf + VS_OFF + wn * KV_EL, qkv_b + 256, wm, g, tig);

    // ---- Q rows (QKV rows 0..127): then overwrite XS ----
    do_gemm(qkv_w, C, smf, tid, wm, wn, g, tig);
    __syncthreads();                      // all B-reads of x done
    {
        float* dst = smf + XS_OFF + wn * XS_EL;
        #pragma unroll
        for (int mt = 0; mt < 2; ++mt) {
            const int r0 = wm * 32 + mt * 16 + g;
            const float bz0 = __ldg(qkv_b + r0);
            const float bz1 = __ldg(qkv_b + r0 + 8);
            #pragma unroll
            for (int nt = 0; nt < 4; ++nt) {
                const int bn = nt * 8 + 2 * tig;
                // XS_PAD=36 (even): offsets even -> float2 aligned
                *(float2*)(dst + r0 * XS_PAD + bn) =
                    tf2pair(C[mt][nt][0] + bz0, C[mt][nt][1] + bz0);
                *(float2*)(dst + (r0 + 8) * XS_PAD + bn) =
                    tf2pair(C[mt][nt][2] + bz1, C[mt][nt][3] + bz1);
            }
        }
    }
    __syncthreads();

    // ---- attention: 8 tasks (el, h), 1 per warp ----
    {
        const int el = warp >> 2;        // 0..1
        const int h  = warp & 3;         // 0..3
        const float* Qb = smf + XS_OFF + el * XS_EL + (h * 32) * XS_PAD;
        float*       Kb = smf + KS_OFF + el * KV_EL + (h * 32) * KV_PAD;
        const float* Vb = smf + VS_OFF + el * KV_EL + (h * 32) * KV_PAD;

        // scores = Q K^T : M=32(q) N=32(m) K=32(d)
        float s[2][4][4];
        #pragma unroll
        for (int mt = 0; mt < 2; ++mt)
            #pragma unroll
            for (int nt = 0; nt < 4; ++nt)
                #pragma unroll
                for (int r = 0; r < 4; ++r) s[mt][nt][r] = 0.0f;

        #pragma unroll
        for (int kt = 0; kt < 4; ++kt) {
            unsigned bf[4][2];
            #pragma unroll
            for (int nt = 0; nt < 4; ++nt) {
                const float* bp = Kb + (kt * 8 + tig) * KV_PAD + nt * 8 + g;
                bf[nt][0] = __float_as_uint(bp[0]);
                bf[nt][1] = __float_as_uint(bp[4 * KV_PAD]);
            }
            #pragma unroll
            for (int mt = 0; mt < 2; ++mt) {
                const float* ap = Qb + (kt * 8 + tig) * XS_PAD + mt * 16 + g;
                unsigned a0 = __float_as_uint(ap[0]);
                unsigned a1 = __float_as_uint(ap[8]);
                unsigned a2 = __float_as_uint(ap[4 * XS_PAD]);
                unsigned a3 = __float_as_uint(ap[4 * XS_PAD + 8]);
                #pragma unroll
                for (int nt = 0; nt < 4; ++nt)
                    mma8(s[mt][nt], a0, a1, a2, a3, bf[nt][0], bf[nt][1]);
            }
        }

        // scale + rel-pos bias + softmax (per row, quad shfl reduce)
        #pragma unroll
        for (int mt = 0; mt < 2; ++mt) {
            #pragma unroll
            for (int half = 0; half < 2; ++half) {
                const int q = mt * 16 + g + half * 8;
                float mx = -1e30f;
                #pragma unroll
                for (int nt = 0; nt < 4; ++nt)
                    #pragma unroll
                    for (int p = 0; p < 2; ++p) {
                        const int m = nt * 8 + 2 * tig + p;
                        float v = s[mt][nt][half * 2 + p] * ATT_SCALE
                                + smf[RL_OFF + (m - q + 31) * 4 + h];
                        s[mt][nt][half * 2 + p] = v;
                        mx = fmaxf(mx, v);
                    }
                mx = fmaxf(mx, __shfl_xor_sync(0xffffffffu, mx, 1));
                mx = fmaxf(mx, __shfl_xor_sync(0xffffffffu, mx, 2));
                float sum = 0.0f;
                #pragma unroll
                for (int nt = 0; nt < 4; ++nt)
                    #pragma unroll
                    for (int p = 0; p < 2; ++p) {
                        float v = __expf(s[mt][nt][half * 2 + p] - mx);
                        s[mt][nt][half * 2 + p] = v;
                        sum += v;
                    }
                sum += __shfl_xor_sync(0xffffffffu, sum, 1);
                sum += __shfl_xor_sync(0xffffffffu, sum, 2);
                const float inv = 1.0f / sum;
                #pragma unroll
                for (int nt = 0; nt < 4; ++nt)
                    #pragma unroll
                    for (int p = 0; p < 2; ++p) s[mt][nt][half * 2 + p] *= inv;
            }
        }

        __syncwarp();
        // P -> Kb rows (K of this task is dead), tf32. Scalar stores (pad 33!).
        #pragma unroll
        for (int mt = 0; mt < 2; ++mt) {
            const int q0 = mt * 16 + g;
            #pragma unroll
            for (int nt = 0; nt < 4; ++nt) {
                const int m = nt * 8 + 2 * tig;
                Kb[q0 * KV_PAD + m]           = __uint_as_float(f2tf(s[mt][nt][0]));
                Kb[q0 * KV_PAD + m + 1]       = __uint_as_float(f2tf(s[mt][nt][1]));
                Kb[(q0 + 8) * KV_PAD + m]     = __uint_as_float(f2tf(s[mt][nt][2]));
                Kb[(q0 + 8) * KV_PAD + m + 1] = __uint_as_float(f2tf(s[mt][nt][3]));
            }
        }
        __syncwarp();

        // out = P V : M=32(q) N=32(d) K=32(m)
        float o[2][4][4];
        #pragma unroll
        for (int mt = 0; mt < 2; ++mt)
            #pragma unroll
            for (int nt = 0; nt < 4; ++nt)
                #pragma unroll
                for (int r = 0; r < 4; ++r) o[mt][nt][r] = 0.0f;

        #pragma unroll
        for (int kt = 0; kt < 4; ++kt) {
            unsigned bf[4][2];
            #pragma unroll
            for (int nt = 0; nt < 4; ++nt) {
                const float* bp = Vb + (nt * 8 + g) * KV_PAD + kt * 8 + tig;
                bf[nt][0] = __float_as_uint(bp[0]);
                bf[nt][1] = __float_as_uint(bp[4]);
            }
            #pragma unroll
            for (int mt = 0; mt < 2; ++mt) {
                const float* ap = Kb + (mt * 16 + g) * KV_PAD + kt * 8 + tig;
                unsigned a0 = __float_as_uint(ap[0]);
                unsigned a1 = __float_as_uint(ap[8 * KV_PAD]);
                unsigned a2 = __float_as_uint(ap[4]);
                unsigned a3 = __float_as_uint(ap[8 * KV_PAD + 4]);
                #pragma unroll
                for (int nt = 0; nt < 4; ++nt)
                    mma8(o[mt][nt], a0, a1, a2, a3, bf[nt][0], bf[nt][1]);
            }
        }
        __syncwarp();

        // att -> XS rows of this (el, h) (own Q rows, dead), transposed
        float* Ab = smf + XS_OFF + el * XS_EL + (h * 32) * XS_PAD;
        #pragma unroll
        for (int mt = 0; mt < 2; ++mt) {
            const int q = mt * 16 + g;
            #pragma unroll
            for (int nt = 0; nt < 4; ++nt) {
                const int d = nt * 8 + 2 * tig;
                Ab[d * XS_PAD + q]           = __uint_as_float(f2tf(o[mt][nt][0]));
                Ab[(d + 1) * XS_PAD + q]     = __uint_as_float(f2tf(o[mt][nt][1]));
                Ab[d * XS_PAD + q + 8]       = __uint_as_float(f2tf(o[mt][nt][2]));
                Ab[(d + 1) * XS_PAD + q + 8] = __uint_as_float(f2tf(o[mt][nt][3]));
            }
        }
    }
    __syncthreads();

    // ---- output projection (B = att in XS) + bias + residual + stats ----
    do_gemm(out_w, C, smf, tid, wm, wn, g, tig);

    // Panel is dead now; reuse it as the stats buffer (ST_OFF aliases PN_OFF).
    __syncthreads();                      // all panel reads done
    if (tid < 256) smf[ST_OFF + tid] = 0.0f;
    __syncthreads();

    #pragma unroll
    for (int mt = 0; mt < 2; ++mt) {
        const int r0 = wm * 32 + mt * 16 + g;
        const float ob0 = __ldg(out_b + r0);
        const float ob1 = __ldg(out_b + r0 + 8);
        float su0 = 0.f, sq0 = 0.f, su1 = 0.f, sq1 = 0.f;
        #pragma unroll
        for (int nt = 0; nt < 4; ++nt) {
            const int bin = nt * 8 + 2 * tig;
            const size_t ga = (size_t)(b0 + wn) * (CCH * NB) + (size_t)r0 * NB + bin;
            float2 rx = *(const float2*)(x + ga);
            const float v0 = C[mt][nt][0] + ob0 + rx.x;
            const float v1 = C[mt][nt][1] + ob0 + rx.y;
            *(float2*)(out + ga) = make_float2(v0, v1);
            su0 += v0 + v1; sq0 += v0 * v0 + v1 * v1;
            const size_t gb = ga + 8 * NB;
            float2 ry = *(const float2*)(x + gb);
            const float v2 = C[mt][nt][2] + ob1 + ry.x;
            const float v3 = C[mt][nt][3] + ob1 + ry.y;
            *(float2*)(out + gb) = make_float2(v2, v3);
            su1 += v2 + v3; sq1 += v2 * v2 + v3 * v3;
        }
        su0 += __shfl_xor_sync(0xffffffffu, su0, 1); su0 += __shfl_xor_sync(0xffffffffu, su0, 2);
        sq0 += __shfl_xor_sync(0xffffffffu, sq0, 1); sq0 += __shfl_xor_sync(0xffffffffu, sq0, 2);
        su1 += __shfl_xor_sync(0xffffffffu, su1, 1); su1 += __shfl_xor_sync(0xffffffffu, su1, 2);
        sq1 += __shfl_xor_sync(0xffffffffu, sq1, 1); sq1 += __shfl_xor_sync(0xffffffffu, sq1, 2);
        if (tig == 0) {
            atomicAdd(&smf[ST_OFF + r0], su0);
            atomicAdd(&smf[ST_OFF + 128 + r0], sq0);
            atomicAdd(&smf[ST_OFF + r0 + 8], su1);
            atomicAdd(&smf[ST_OFF + 128 + r0 + 8], sq1);
        }
    }
    __syncthreads();
    if (tid < 128) {
        atomicAdd(&g_stats[tid], smf[ST_OFF + tid]);
        atomicAdd(&g_stats[128 + tid], smf[ST_OFF + 128 + tid]);
    }
}

__global__ void bn_finalize_kernel(const float* __restrict__ gamma,
                                   const float* __restrict__ beta)
{
    const int c = threadIdx.x;
    const float inv_m = 1.0f / (float)MTOT;
    const float mean  = g_stats[c] * inv_m;
    const float var   = g_stats[128 + c] * inv_m - mean * mean;
    const float rstd  = rsqrtf(var + BN_EPS);
    const float sc    = gamma[c] * rstd;
    g_stats[256 + c] = sc;
    g_stats[384 + c] = beta[c] - mean * sc;
}

// 2 float4 per thread at half-array stride (same channel both halves).
__global__ __launch_bounds__(256)
void bn_apply_kernel(float* __restrict__ out)
{
    const int idx = blockIdx.x * blockDim.x + threadIdx.x;   // float4 idx, first half
    float4* o4 = (float4*)out;
    const int row = idx >> 3;
    const int c   = row & (CCH - 1);
    const float sc = g_stats[256 + c];
    const float sh = g_stats[384 + c];
    float4 a = o4[idx];
    float4 b = o4[idx + 4194304];
    a.x = a.x * sc + sh; a.y = a.y * sc + sh;
    a.z = a.z * sc + sh; a.w = a.w * sc + sh;
    b.x = b.x * sc + sh; b.y = b.y * sc + sh;
    b.z = b.z * sc + sh; b.w = b.w * sc + sh;
    o4[idx] = a;
    o4[idx + 4194304] = b;
}

extern "C" void kernel_launch(void* const* d_in, const int* in_sizes, int n_in,
                              void* d_out, int out_size)
{
    const float* x      = (const float*)d_in[0];
    const float* qkv_w  = (const float*)d_in[1];
    const float* qkv_b  = (const float*)d_in[2];
    const float* out_w  = (const float*)d_in[3];
    const float* out_b  = (const float*)d_in[4];
    const float* rel    = (const float*)d_in[5];
    const float* gamma  = (const float*)d_in[6];
    const float* beta   = (const float*)d_in[7];
    float* out = (float*)d_out;

    cudaFuncSetAttribute(fa_main_kernel,
                         cudaFuncAttributeMaxDynamicSharedMemorySize,
                         SM_FLOATS * sizeof(float));

    zero_stats_kernel<<<1, 512>>>();
    fa_main_kernel<<<BATCH / 2, 256, SM_FLOATS * sizeof(float)>>>(
        x, qkv_w, qkv_b, out_w, out_b, rel, out);
    bn_finalize_kernel<<<1, 128>>>(gamma, beta);
    bn_apply_kernel<<<16384, 256>>>(out);
}

// round 15
// speedup vs baseline: 1.1961x; 1.1961x over previous
#include <cuda_runtime.h>
#include <cstdint>

// FrequencyAttention v5: mma.sync tf32 (sm_103 has NO tcgen05 — harness targets
// plain sm_103). Compose of proven parts: R8's pad-40 conflict-free smem map +
// R9's 512-thread / 16-warp tiling. Single weight panel. 4 els/CTA, grid 2048.

#define BATCH 8192
#define CCH   128
#define NB    32
#define ATT_SCALE 0.17677669529663687f
#define BN_EPS 1e-5f
#define MTOT  (BATCH * NB)

// ---- shared memory layout (float offsets) — R8's proven map ----
#define XS_PAD 40
#define XS_EL  (128 * XS_PAD)            // 5120
#define XS_OFF 0                          // x -> Q -> att : [4][128][40]
#define KV_PAD 33
#define KV_EL  (128 * KV_PAD)            // 4224
#define KS_OFF 20480                      // K (later P) : [4][128][33]
#define VS_OFF (KS_OFF + 4 * KV_EL)      // 37376  V : [4][128][33]
#define PN_PAD 20
#define PN_OFF (VS_OFF + 4 * KV_EL)      // 54272  weight panel [128][20]
#define RL_OFF (PN_OFF + 128 * PN_PAD)   // 56832  rel bias (252 used)
#define ST_OFF (RL_OFF + 256)            // 57088  stats [sum 128][sq 128]
#define SM_FLOATS (ST_OFF + 256)         // 57344 floats = 229376 bytes

__device__ float g_stats[512];

__global__ void zero_stats_kernel() { g_stats[threadIdx.x] = 0.0f; }

__device__ __forceinline__ unsigned f2tf(float f) {
    unsigned u;
    asm("cvt.rna.tf32.f32 %0, %1;" : "=r"(u) : "f"(f));
    return u;
}

__device__ __forceinline__ float2 tf2pair(float a, float b) {
    float2 r;
    r.x = __uint_as_float(f2tf(a));
    r.y = __uint_as_float(f2tf(b));
    return r;
}

__device__ __forceinline__ void mma8(float c[4],
                                     unsigned a0, unsigned a1, unsigned a2, unsigned a3,
                                     unsigned b0, unsigned b1) {
    asm volatile(
        "mma.sync.aligned.m16n8k8.row.col.f32.tf32.tf32.f32 "
        "{%0,%1,%2,%3},{%4,%5,%6,%7},{%8,%9},{%0,%1,%2,%3};\n"
        : "+f"(c[0]), "+f"(c[1]), "+f"(c[2]), "+f"(c[3])
        : "r"(a0), "r"(a1), "r"(a2), "r"(a3), "r"(b0), "r"(b1));
}

// M=128,N=128,K=128 GEMM. A = f32 weights via single smem panel (tf32).
// B = XS region (tf32 bits, pad 40 -> bank 8*tig+g, conflict-free).
// 16 warps: warp tile 32x32 (wm=warp>>2 M quarter, wn=warp&3 el).
__device__ __forceinline__ void do_gemm(const float* __restrict__ W,
                                        float C[2][4][4], float* smf,
                                        int tid, int wm, int wn, int g, int tig)
{
    float* panel = smf + PN_OFF;
    const float* B = smf + XS_OFF + wn * XS_EL;

    #pragma unroll
    for (int mt = 0; mt < 2; ++mt)
        #pragma unroll
        for (int nt = 0; nt < 4; ++nt)
            #pragma unroll
            for (int r = 0; r < 4; ++r) C[mt][nt][r] = 0.0f;

    const int pr = tid >> 2;             // panel row (0..127), 4 threads/row
    const int pc = (tid & 3) * 4;        // col chunk (4 floats)
    const float* wrow = W + pr * 128 + pc;

    float4 w = __ldg((const float4*)wrow);

    for (int ks = 0; ks < 8; ++ks) {
        __syncthreads();                  // previous panel fully consumed
        {
            uint4 u = make_uint4(f2tf(w.x), f2tf(w.y), f2tf(w.z), f2tf(w.w));
            *(uint4*)(panel + pr * PN_PAD + pc) = u;
        }
        __syncthreads();
        if (ks < 7) w = __ldg((const float4*)(wrow + (ks + 1) * 16));
        #pragma unroll
        for (int kk = 0; kk < 2; ++kk) {
            unsigned bf[4][2];
            #pragma unroll
            for (int nt = 0; nt < 4; ++nt) {
                const float* bp = B + (ks * 16 + kk * 8 + tig) * XS_PAD + nt * 8 + g;
                bf[nt][0] = __float_as_uint(bp[0]);
                bf[nt][1] = __float_as_uint(bp[4 * XS_PAD]);
            }
            #pragma unroll
            for (int mt = 0; mt < 2; ++mt) {
                const float* ap = panel + (wm * 32 + mt * 16 + g) * PN_PAD + kk * 8 + tig;
                unsigned a0 = __float_as_uint(ap[0]);
                unsigned a1 = __float_as_uint(ap[8 * PN_PAD]);
                unsigned a2 = __float_as_uint(ap[4]);
                unsigned a3 = __float_as_uint(ap[8 * PN_PAD + 4]);
                #pragma unroll
                for (int nt = 0; nt < 4; ++nt)
                    mma8(C[mt][nt], a0, a1, a2, a3, bf[nt][0], bf[nt][1]);
            }
        }
    }
}

// KV region pad 33 = odd -> SCALAR stores only (misaligned ST.64 traps; R6).
__device__ __forceinline__ void store_kv(const float C[2][4][4], float* dst,
                                         const float* __restrict__ bias,
                                         int wm, int g, int tig)
{
    #pragma unroll
    for (int mt = 0; mt < 2; ++mt) {
        const int r0 = wm * 32 + mt * 16 + g;
        const float bz0 = __ldg(bias + r0);
        const float bz1 = __ldg(bias + r0 + 8);
        #pragma unroll
        for (int nt = 0; nt < 4; ++nt) {
            const int m = nt * 8 + 2 * tig;
            dst[r0 * KV_PAD + m]           = __uint_as_float(f2tf(C[mt][nt][0] + bz0));
            dst[r0 * KV_PAD + m + 1]       = __uint_as_float(f2tf(C[mt][nt][1] + bz0));
            dst[(r0 + 8) * KV_PAD + m]     = __uint_as_float(f2tf(C[mt][nt][2] + bz1));
            dst[(r0 + 8) * KV_PAD + m + 1] = __uint_as_float(f2tf(C[mt][nt][3] + bz1));
        }
    }
}

__global__ __launch_bounds__(512, 1)
void fa_main_kernel(const float* __restrict__ x,
                    const float* __restrict__ qkv_w,
                    const float* __restrict__ qkv_b,
                    const float* __restrict__ out_w,
                    const float* __restrict__ out_b,
                    const float* __restrict__ rel,
                    float* __restrict__ out)
{
    extern __shared__ float smf[];
    const int tid  = threadIdx.x;
    const int warp = tid >> 5;           // 0..15
    const int lane = tid & 31;
    const int g    = lane >> 2;
    const int tig  = lane & 3;
    const int wm   = warp >> 2;          // 0..3  (M quarter)
    const int wn   = warp & 3;           // 0..3  (el)
    const int b0   = blockIdx.x * 4;

    if (tid < 252) smf[RL_OFF + tid] = __ldg(&rel[tid]);
    if (tid < 256) smf[ST_OFF + tid] = 0.0f;

    // ---- load x (4 els) into XS as tf32 bits ----
    {
        const float4* xg = (const float4*)(x + (size_t)b0 * (CCH * NB));
        #pragma unroll
        for (int j = 0; j < 8; ++j) {
            const int i4  = tid + j * 512;          // 4096 float4 total
            float4 v = __ldg(xg + i4);
            const int el  = i4 >> 10;
            const int c   = (i4 >> 3) & 127;
            const int bn  = (i4 & 7) * 4;
            unsigned* d = (unsigned*)(smf + XS_OFF + el * XS_EL + c * XS_PAD + bn);
            ((uint4*)d)[0] = make_uint4(f2tf(v.x), f2tf(v.y), f2tf(v.z), f2tf(v.w));
        }
    }
    __syncthreads();

    float C[2][4][4];

    do_gemm(qkv_w + 128 * 128, C, smf, tid, wm, wn, g, tig);
    store_kv(C, smf + KS_OFF + wn * KV_EL, qkv_b + 128, wm, g, tig);

    do_gemm(qkv_w + 256 * 128, C, smf, tid, wm, wn, g, tig);
    store_kv(C, smf + VS_OFF + wn * KV_EL, qkv_b + 256, wm, g, tig);

    do_gemm(qkv_w, C, smf, tid, wm, wn, g, tig);
    __syncthreads();                      // all B-reads of x done
    {
        float* dst = smf + XS_OFF + wn * XS_EL;
        #pragma unroll
        for (int mt = 0; mt < 2; ++mt) {
            const int r0 = wm * 32 + mt * 16 + g;
            const float bz0 = __ldg(qkv_b + r0);
            const float bz1 = __ldg(qkv_b + r0 + 8);
            #pragma unroll
            for (int nt = 0; nt < 4; ++nt) {
                const int bn = nt * 8 + 2 * tig;
                *(float2*)(dst + r0 * XS_PAD + bn) =
                    tf2pair(C[mt][nt][0] + bz0, C[mt][nt][1] + bz0);
                *(float2*)(dst + (r0 + 8) * XS_PAD + bn) =
                    tf2pair(C[mt][nt][2] + bz1, C[mt][nt][3] + bz1);
            }
        }
    }
    __syncthreads();

    // ---- attention: 16 tasks (el, h), 1 per warp ----
    {
        const int el = warp >> 2;
        const int h  = warp & 3;
        const float* Qb = smf + XS_OFF + el * XS_EL + (h * 32) * XS_PAD;
        float*       Kb = smf + KS_OFF + el * KV_EL + (h * 32) * KV_PAD;
        const float* Vb = smf + VS_OFF + el * KV_EL + (h * 32) * KV_PAD;

        float s[2][4][4];
        #pragma unroll
        for (int mt = 0; mt < 2; ++mt)
            #pragma unroll
            for (int nt = 0; nt < 4; ++nt)
                #pragma unroll
                for (int r = 0; r < 4; ++r) s[mt][nt][r] = 0.0f;

        #pragma unroll
        for (int kt = 0; kt < 4; ++kt) {
            unsigned bf[4][2];
            #pragma unroll
            for (int nt = 0; nt < 4; ++nt) {
                const float* bp = Kb + (kt * 8 + tig) * KV_PAD + nt * 8 + g;
                bf[nt][0] = __float_as_uint(bp[0]);
                bf[nt][1] = __float_as_uint(bp[4 * KV_PAD]);
            }
            #pragma unroll
            for (int mt = 0; mt < 2; ++mt) {
                const float* ap = Qb + (kt * 8 + tig) * XS_PAD + mt * 16 + g;
                unsigned a0 = __float_as_uint(ap[0]);
                unsigned a1 = __float_as_uint(ap[8]);
                unsigned a2 = __float_as_uint(ap[4 * XS_PAD]);
                unsigned a3 = __float_as_uint(ap[4 * XS_PAD + 8]);
                #pragma unroll
                for (int nt = 0; nt < 4; ++nt)
                    mma8(s[mt][nt], a0, a1, a2, a3, bf[nt][0], bf[nt][1]);
            }
        }

        #pragma unroll
        for (int mt = 0; mt < 2; ++mt) {
            #pragma unroll
            for (int half = 0; half < 2; ++half) {
                const int q = mt * 16 + g + half * 8;
                float mx = -1e30f;
                #pragma unroll
                for (int nt = 0; nt < 4; ++nt)
                    #pragma unroll
                    for (int p = 0; p < 2; ++p) {
                        const int m = nt * 8 + 2 * tig + p;
                        float v = s[mt][nt][half * 2 + p] * ATT_SCALE
                                + smf[RL_OFF + (m - q + 31) * 4 + h];
                        s[mt][nt][half * 2 + p] = v;
                        mx = fmaxf(mx, v);
                    }
                mx = fmaxf(mx, __shfl_xor_sync(0xffffffffu, mx, 1));
                mx = fmaxf(mx, __shfl_xor_sync(0xffffffffu, mx, 2));
                float sum = 0.0f;
                #pragma unroll
                for (int nt = 0; nt < 4; ++nt)
                    #pragma unroll
                    for (int p = 0; p < 2; ++p) {
                        float v = __expf(s[mt][nt][half * 2 + p] - mx);
                        s[mt][nt][half * 2 + p] = v;
                        sum += v;
                    }
                sum += __shfl_xor_sync(0xffffffffu, sum, 1);
                sum += __shfl_xor_sync(0xffffffffu, sum, 2);
                const float inv = 1.0f / sum;
                #pragma unroll
                for (int nt = 0; nt < 4; ++nt)
                    #pragma unroll
                    for (int p = 0; p < 2; ++p) s[mt][nt][half * 2 + p] *= inv;
            }
        }

        __syncwarp();
        #pragma unroll
        for (int mt = 0; mt < 2; ++mt) {            // P -> Kb (pad 33: scalar!)
            const int q0 = mt * 16 + g;
            #pragma unroll
            for (int nt = 0; nt < 4; ++nt) {
                const int m = nt * 8 + 2 * tig;
                Kb[q0 * KV_PAD + m]           = __uint_as_float(f2tf(s[mt][nt][0]));
                Kb[q0 * KV_PAD + m + 1]       = __uint_as_float(f2tf(s[mt][nt][1]));
                Kb[(q0 + 8) * KV_PAD + m]     = __uint_as_float(f2tf(s[mt][nt][2]));
                Kb[(q0 + 8) * KV_PAD + m + 1] = __uint_as_float(f2tf(s[mt][nt][3]));
            }
        }
        __syncwarp();

        float o[2][4][4];
        #pragma unroll
        for (int mt = 0; mt < 2; ++mt)
            #pragma unroll
            for (int nt = 0; nt < 4; ++nt)
                #pragma unroll
                for (int r = 0; r < 4; ++r) o[mt][nt][r] = 0.0f;

        #pragma unroll
        for (int kt = 0; kt < 4; ++kt) {
            unsigned bf[4][2];
            #pragma unroll
            for (int nt = 0; nt < 4; ++nt) {
                const float* bp = Vb + (nt * 8 + g) * KV_PAD + kt * 8 + tig;
                bf[nt][0] = __float_as_uint(bp[0]);
                bf[nt][1] = __float_as_uint(bp[4]);
            }
            #pragma unroll
            for (int mt = 0; mt < 2; ++mt) {
                const float* ap = Kb + (mt * 16 + g) * KV_PAD + kt * 8 + tig;
                unsigned a0 = __float_as_uint(ap[0]);
                unsigned a1 = __float_as_uint(ap[8 * KV_PAD]);
                unsigned a2 = __float_as_uint(ap[4]);
                unsigned a3 = __float_as_uint(ap[8 * KV_PAD + 4]);
                #pragma unroll
                for (int nt = 0; nt < 4; ++nt)
                    mma8(o[mt][nt], a0, a1, a2, a3, bf[nt][0], bf[nt][1]);
            }
        }
        __syncwarp();

        float* Ab = smf + XS_OFF + el * XS_EL + (h * 32) * XS_PAD;
        #pragma unroll
        for (int mt = 0; mt < 2; ++mt) {            // att -> XS transposed
            const int q = mt * 16 + g;
            #pragma unroll
            for (int nt = 0; nt < 4; ++nt) {
                const int d = nt * 8 + 2 * tig;
                Ab[d * XS_PAD + q]           = __uint_as_float(f2tf(o[mt][nt][0]));
                Ab[(d + 1) * XS_PAD + q]     = __uint_as_float(f2tf(o[mt][nt][1]));
                Ab[d * XS_PAD + q + 8]       = __uint_as_float(f2tf(o[mt][nt][2]));
                Ab[(d + 1) * XS_PAD + q + 8] = __uint_as_float(f2tf(o[mt][nt][3]));
            }
        }
    }
    __syncthreads();

    // ---- output projection + bias + residual + stats ----
    do_gemm(out_w, C, smf, tid, wm, wn, g, tig);

    #pragma unroll
    for (int mt = 0; mt < 2; ++mt) {
        const int r0 = wm * 32 + mt * 16 + g;
        const float ob0 = __ldg(out_b + r0);
        const float ob1 = __ldg(out_b + r0 + 8);
        float su0 = 0.f, sq0 = 0.f, su1 = 0.f, sq1 = 0.f;
        #pragma unroll
        for (int nt = 0; nt < 4; ++nt) {
            const int bin = nt * 8 + 2 * tig;
            const size_t ga = (size_t)(b0 + wn) * (CCH * NB) + (size_t)r0 * NB + bin;
            float2 rx = *(const float2*)(x + ga);
            const float v0 = C[mt][nt][0] + ob0 + rx.x;
            const float v1 = C[mt][nt][1] + ob0 + rx.y;
            *(float2*)(out + ga) = make_float2(v0, v1);
            su0 += v0 + v1; sq0 += v0 * v0 + v1 * v1;
            const size_t gb = ga + 8 * NB;
            float2 ry = *(const float2*)(x + gb);
            const float v2 = C[mt][nt][2] + ob1 + ry.x;
            const float v3 = C[mt][nt][3] + ob1 + ry.y;
            *(float2*)(out + gb) = make_float2(v2, v3);
            su1 += v2 + v3; sq1 += v2 * v2 + v3 * v3;
        }
        su0 += __shfl_xor_sync(0xffffffffu, su0, 1); su0 += __shfl_xor_sync(0xffffffffu, su0, 2);
        sq0 += __shfl_xor_sync(0xffffffffu, sq0, 1); sq0 += __shfl_xor_sync(0xffffffffu, sq0, 2);
        su1 += __shfl_xor_sync(0xffffffffu, su1, 1); su1 += __shfl_xor_sync(0xffffffffu, su1, 2);
        sq1 += __shfl_xor_sync(0xffffffffu, sq1, 1); sq1 += __shfl_xor_sync(0xffffffffu, sq1, 2);
        if (tig == 0) {
            atomicAdd(&smf[ST_OFF + r0], su0);
            atomicAdd(&smf[ST_OFF + 128 + r0], sq0);
            atomicAdd(&smf[ST_OFF + r0 + 8], su1);
            atomicAdd(&smf[ST_OFF + 128 + r0 + 8], sq1);
        }
    }
    __syncthreads();
    if (tid < 128) {
        atomicAdd(&g_stats[tid], smf[ST_OFF + tid]);
        atomicAdd(&g_stats[128 + tid], smf[ST_OFF + 128 + tid]);
    }
}

__global__ void bn_finalize_kernel(const float* __restrict__ gamma,
                                   const float* __restrict__ beta)
{
    const int c = threadIdx.x;
    const float inv_m = 1.0f / (float)MTOT;
    const float mean  = g_stats[c] * inv_m;
    const float var   = g_stats[128 + c] * inv_m - mean * mean;
    const float rstd  = rsqrtf(var + BN_EPS);
    const float sc    = gamma[c] * rstd;
    g_stats[256 + c] = sc;
    g_stats[384 + c] = beta[c] - mean * sc;
}

__global__ __launch_bounds__(256)
void bn_apply_kernel(float* __restrict__ out)
{
    const int idx = blockIdx.x * blockDim.x + threadIdx.x;
    float4* o4 = (float4*)out;
    const int row = idx >> 3;
    const int c   = row & (CCH - 1);
    const float sc = g_stats[256 + c];
    const float sh = g_stats[384 + c];
    float4 a = o4[idx];
    float4 b = o4[idx + 4194304];
    a.x = a.x * sc + sh; a.y = a.y * sc + sh;
    a.z = a.z * sc + sh; a.w = a.w * sc + sh;
    b.x = b.x * sc + sh; b.y = b.y * sc + sh;
    b.z = b.z * sc + sh; b.w = b.w * sc + sh;
    o4[idx] = a;
    o4[idx + 4194304] = b;
}

extern "C" void kernel_launch(void* const* d_in, const int* in_sizes, int n_in,
                              void* d_out, int out_size)
{
    const float* x      = (const float*)d_in[0];
    const float* qkv_w  = (const float*)d_in[1];
    const float* qkv_b  = (const float*)d_in[2];
    const float* out_w  = (const float*)d_in[3];
    const float* out_b  = (const float*)d_in[4];
    const float* rel    = (const float*)d_in[5];
    const float* gamma  = (const float*)d_in[6];
    const float* beta   = (const float*)d_in[7];
    float* out = (float*)d_out;

    cudaFuncSetAttribute(fa_main_kernel,
                         cudaFuncAttributeMaxDynamicSharedMemorySize,
                         SM_FLOATS * sizeof(float));

    zero_stats_kernel<<<1, 512>>>();
    fa_main_kernel<<<BATCH / 4, 512, SM_FLOATS * sizeof(float)>>>(
        x, qkv_w, qkv_b, out_w, out_b, rel, out);
    bn_finalize_kernel<<<1, 128>>>(gamma, beta);
    bn_apply_kernel<<<16384, 256>>>(out);
}